// round 13
// baseline (speedup 1.0000x reference)
#include <cuda_runtime.h>
#include <cuda_fp16.h>

// BackProjection: B=2, A=180, HR=512, H=W=512, pad=51, Hp=Wp=614
#define A_N   180
#define HR_N  512
#define HOUT  512
#define HP    614
#define PADR  64            // zero-pad rows each side (covers y0 in [-56, 667])
#define HPP   (HP + 2*PADR) // 742 rows per angle
#define MAGICF 12582912.0f  // 1.5 * 2^23
#define MAGICI 0x4B400000u  // float bits of 12582912.0f

// Zero-padded per-angle column profile in fp16, both batches + next row fused:
// entry.x = half2(b0[y], b1[y]); entry.y = half2(b0[y+1], b1[y+1]),
// with b*[y] == 0 outside [0, HP-1]. One LDG.64 gives a full bilinear-y pair
// for both batches. Zero-initialized; col_kernel writes each value once into
// row y (.x) and row y-1 (.y).
__device__ uint2 g_colh[A_N * HPP];

__device__ __forceinline__ float2 col_at(const float* __restrict__ sino, int a, int y) {
    float src = ((float)y + 0.5f) * ((float)HR_N / (float)HP) - 0.5f;
    src = fminf(fmaxf(src, 0.0f), (float)(HR_N - 1));
    int i0 = (int)src;                       // src >= 0
    int i1 = min(i0 + 1, HR_N - 1);
    float w = src - (float)i0;
    const float* s0 = sino + a * HR_N;                 // b = 0
    const float* s1 = sino + A_N * HR_N + a * HR_N;    // b = 1
    // match reference rounding: p0*(1-w) + p1*w
    float v0 = s0[i0] * (1.0f - w) + s0[i1] * w;
    float v1 = s1[i0] * (1.0f - w) + s1[i1] * w;
    return make_float2(v0, v1);
}

__global__ void col_kernel(const float* __restrict__ sino) {
    int idx = blockIdx.x * blockDim.x + threadIdx.x;
    if (idx >= A_N * HPP) return;
    int a  = idx / HPP;
    int y  = idx - a * HPP - PADR;          // logical row
    float2 c0 = (y >= 0 && y < HP) ? col_at(sino, a, y) : make_float2(0.f, 0.f);
    __half2 h0 = __floats2half2_rn(c0.x, c0.y);
    unsigned u = *reinterpret_cast<unsigned*>(&h0);
    // row idx: .x = col[y];  row idx-1: .y = col[(y-1)+1] = col[y].
    // Cross-angle boundary: both values are 0 either way. Last row's .y is
    // never written and stays zero-init = correct.
    reinterpret_cast<unsigned*>(&g_colh[idx])[0] = u;
    if (idx > 0)
        reinterpret_cast<unsigned*>(&g_colh[idx - 1])[1] = u;
}

__device__ __forceinline__ __half2 lerp_h2(uint2 cc, float w) {
    __half2 lo = *reinterpret_cast<__half2*>(&cc.x);
    __half2 hi = *reinterpret_cast<__half2*>(&cc.y);
    return __hfma2(__hsub2(hi, lo), __float2half2_rn(w), lo);
}

__global__ __launch_bounds__(256, 7) void bp_kernel(const float* __restrict__ angles,
                                                    float* __restrict__ out) {
    __shared__ float2 sh_cs[A_N];   // (cos, sin) of th = -deg2rad(angle)
    int t = threadIdx.y * 32 + threadIdx.x;
    if (t < A_N) {
        float th = -angles[t] * 0.017453292519943295f;
        sh_cs[t] = make_float2(cosf(th), sinf(th));
    }
    __syncthreads();

    // 32x1 warp layout, 1 pixel/thread (proven best occupancy/latency balance).
    int x = blockIdx.x * 32 + threadIdx.x;
    int y = blockIdx.y * 8 + threadIdx.y;
    // padded coords (x+51), center 306.5:  X = (x+51) - 306.5 = x - 255.5
    float Xp = (float)x - 255.5f;
    float Yp = (float)y - 255.5f;

    float a0x = 0.0f, a0y = 0.0f, a1x = 0.0f, a1y = 0.0f;

    // Magic-floor: fq = (iy-0.5) + 1.5*2^23 -> float bits encode floor(iy)
    // (round-to-even ties give w=0 or w=1; both read correct values from the
    // fused-row table). Bias 0x4B400000 is folded into the base pointer so the
    // gather address is ONE IMAD.WIDE from the raw float bits. This removes
    // the F2I(20)+I2F(20) cvt chain from the critical path.
    const uint2* __restrict__ colB0 =
        (const uint2*)((const char*)(g_colh + PADR) - (unsigned long long)MAGICI * 8ULL);

    // Interior: r^2 < 93500 (r < 305.8) => ix, iy in (0.5, 612.5) for all
    // angles: no masking, wxe == 1, y0 in [0,612]. Warp-uniform branch.
    bool interior = fmaf(Xp, Xp, Yp * Yp) < 93500.0f;

    if (__all_sync(0xffffffffu, interior)) {
        const uint2* __restrict__ colB = colB0;
        #pragma unroll 4
        for (int a = 0; a < A_N; a += 2, colB += 2 * HPP) {
            {
                float2 cs = sh_cs[a];
                float iy2 = fmaf(cs.y, Xp, fmaf(cs.x, Yp, 306.0f));  // iy - 0.5
                float fq  = iy2 + MAGICF;
                float qf  = fq - MAGICF;
                float w   = (iy2 - qf) + 0.5f;
                uint2 cc  = colB[__float_as_uint(fq)];
                float2 rf = __half22float2(lerp_h2(cc, w));
                a0x += rf.x;
                a0y += rf.y;
            }
            {
                float2 cs = sh_cs[a + 1];
                float iy2 = fmaf(cs.y, Xp, fmaf(cs.x, Yp, 306.0f));
                float fq  = iy2 + MAGICF;
                float qf  = fq - MAGICF;
                float w   = (iy2 - qf) + 0.5f;
                uint2 cc  = (colB + HPP)[__float_as_uint(fq)];
                float2 rf = __half22float2(lerp_h2(cc, w));
                a1x += rf.x;
                a1y += rf.y;
            }
        }
    } else {
        // General path. Zero-padded table removes all y masking/clamping;
        // x masking collapses to wxe = clamp(min(ix+1, 614-ix), 0, 1):
        //   ix in [-1,0):  wxe = ix+1;  [0,613): 1;  [613,614): 614-ix; else 0.
        // Magic-floor works for negative floor(iy) too (q in [-55,667],
        // mantissa arithmetic stays linear; bias already in colB0).
        const uint2* __restrict__ colB = colB0;
        #pragma unroll 2
        for (int a = 0; a < A_N; ++a, colB += HPP) {
            float2 cs = sh_cs[a];
            float c = cs.x, s = cs.y;
            float ix  = fmaf(c, Xp, fmaf(-s, Yp, 306.5f));
            float iy2 = fmaf(s, Xp, fmaf(c, Yp, 306.0f));            // iy - 0.5
            float wxe = fmaxf(fminf(fminf(ix + 1.0f, 614.0f - ix), 1.0f), 0.0f);
            float fq  = iy2 + MAGICF;
            float qf  = fq - MAGICF;
            float w   = (iy2 - qf) + 0.5f;
            uint2 cc  = colB[__float_as_uint(fq)];
            float2 rf = __half22float2(lerp_h2(cc, w));
            a0x = fmaf(wxe, rf.x, a0x);
            a0y = fmaf(wxe, rf.y, a0y);
        }
    }

    const float scale = (float)(1.0 / (180.0 + 1e-6));
    int o = y * HOUT + x;
    out[o]               = (a0x + a1x) * scale;
    out[o + HOUT * HOUT] = (a0y + a1y) * scale;   // batch 1 (out shape (2,1,512,512))
}

extern "C" void kernel_launch(void* const* d_in, const int* in_sizes, int n_in,
                              void* d_out, int out_size) {
    const float* sino   = (const float*)d_in[0];
    const float* angles = (const float*)d_in[1];
    float* out = (float*)d_out;

    col_kernel<<<(A_N * HPP + 255) / 256, 256>>>(sino);

    dim3 blk(32, 8);
    dim3 grd(HOUT / 32, HOUT / 8);   // 16 x 64 = 1024 CTAs, single resident wave
    bp_kernel<<<grd, blk>>>(angles, out);
}

// round 15
// speedup vs baseline: 1.5219x; 1.5219x over previous
#include <cuda_runtime.h>
#include <cuda_fp16.h>

// BackProjection: B=2, A=180, HR=512, H=W=512, pad=51, Hp=Wp=614
#define A_N   180
#define HR_N  512
#define HOUT  512
#define HP    614
#define PADR  64            // zero-pad rows each side (covers y0 in [-56, 667])
#define HPP   (HP + 2*PADR) // 742 rows per angle
#define MAGICF 12582912.0f  // 1.5 * 2^23
#define MAGICI 0x4B400000u  // float bits of 12582912.0f

// Zero-padded per-angle column profile in fp16, both batches + next row fused:
// entry.x = half2(b0[y], b1[y]); entry.y = half2(b0[y+1], b1[y+1]),
// with b*[y] == 0 outside [0, HP-1]. One LDG.64 gives a full bilinear-y pair
// for both batches. Zero-initialized; col_kernel writes each value once into
// row y (.x) and row y-1 (.y).
__device__ uint2 g_colh[A_N * HPP];

__device__ __forceinline__ float2 col_at(const float* __restrict__ sino, int a, int y) {
    float src = ((float)y + 0.5f) * ((float)HR_N / (float)HP) - 0.5f;
    src = fminf(fmaxf(src, 0.0f), (float)(HR_N - 1));
    int i0 = (int)src;                       // src >= 0
    int i1 = min(i0 + 1, HR_N - 1);
    float w = src - (float)i0;
    const float* s0 = sino + a * HR_N;                 // b = 0
    const float* s1 = sino + A_N * HR_N + a * HR_N;    // b = 1
    // match reference rounding: p0*(1-w) + p1*w
    float v0 = s0[i0] * (1.0f - w) + s0[i1] * w;
    float v1 = s1[i0] * (1.0f - w) + s1[i1] * w;
    return make_float2(v0, v1);
}

__global__ void col_kernel(const float* __restrict__ sino) {
    int idx = blockIdx.x * blockDim.x + threadIdx.x;
    if (idx >= A_N * HPP) return;
    int a  = idx / HPP;
    int y  = idx - a * HPP - PADR;          // logical row
    float2 c0 = (y >= 0 && y < HP) ? col_at(sino, a, y) : make_float2(0.f, 0.f);
    __half2 h0 = __floats2half2_rn(c0.x, c0.y);
    unsigned u = *reinterpret_cast<unsigned*>(&h0);
    // row idx: .x = col[y];  row idx-1: .y = col[(y-1)+1] = col[y].
    // Cross-angle boundary: both values are 0 either way. Last row's .y is
    // never written and stays zero-init = correct.
    reinterpret_cast<unsigned*>(&g_colh[idx])[0] = u;
    if (idx > 0)
        reinterpret_cast<unsigned*>(&g_colh[idx - 1])[1] = u;
}

__device__ __forceinline__ __half2 lerp_h2(uint2 cc, float w) {
    __half2 lo = *reinterpret_cast<__half2*>(&cc.x);
    __half2 hi = *reinterpret_cast<__half2*>(&cc.y);
    return __hfma2(__hsub2(hi, lo), __float2half2_rn(w), lo);
}

__global__ __launch_bounds__(256, 7) void bp_kernel(const float* __restrict__ angles,
                                                    float* __restrict__ out) {
    __shared__ float2 sh_cs[A_N];   // (cos, sin) of th = -deg2rad(angle)
    int t = threadIdx.y * 32 + threadIdx.x;
    if (t < A_N) {
        float th = -angles[t] * 0.017453292519943295f;
        sh_cs[t] = make_float2(cosf(th), sinf(th));
    }
    __syncthreads();

    // 32x1 warp layout (proven best): coalesced loads/stores, 1 pixel/thread.
    int x = blockIdx.x * 32 + threadIdx.x;
    int y = blockIdx.y * 8 + threadIdx.y;
    // padded coords (x+51), center 306.5:  X = (x+51) - 306.5 = x - 255.5
    float Xp = (float)x - 255.5f;
    float Yp = (float)y - 255.5f;

    float a0x = 0.0f, a0y = 0.0f, a1x = 0.0f, a1y = 0.0f;

    // Interior: r^2 < 93500 (r < 305.8) => ix, iy in (0.5, 612.5) for all
    // angles: no masking, wxe == 1, y0 in [0,612]. Warp-uniform branch so a
    // straddling warp executes exactly ONE of the two loops.
    bool interior = fmaf(Xp, Xp, Yp * Yp) < 93500.0f;

    if (__all_sync(0xffffffffu, interior)) {
        // Interior loop: exactly the R10 structure (best verified: ncu 39.8us).
        const uint2* __restrict__ colA = g_colh + PADR;
        #pragma unroll 4
        for (int a = 0; a < A_N; a += 2, colA += 2 * HPP) {
            {
                float2 cs = sh_cs[a];
                float iy = fmaf(cs.y, Xp, fmaf(cs.x, Yp, 306.5f));
                int   y0 = (int)iy;                 // iy > 0 -> trunc == floor
                float wy = iy - (float)y0;
                uint2 cc = colA[y0];
                float2 rf = __half22float2(lerp_h2(cc, wy));
                a0x += rf.x;
                a0y += rf.y;
            }
            {
                float2 cs = sh_cs[a + 1];
                float iy = fmaf(cs.y, Xp, fmaf(cs.x, Yp, 306.5f));
                int   y0 = (int)iy;
                float wy = iy - (float)y0;
                uint2 cc = colA[HPP + y0];
                float2 rf = __half22float2(lerp_h2(cc, wy));
                a1x += rf.x;
                a1y += rf.y;
            }
        }
    } else {
        // General/corner path (tail-setting stragglers): magic-number floor
        // removes the serial CVT.FLOOR + F2I (~40 cyc) from the chain.
        // fq = (iy-0.5) + 1.5*2^23 -> low mantissa bits encode floor(iy);
        // bias MAGICI folded into the base pointer (one IMAD.WIDE to address).
        // Round-to-even ties give w=0 or w=1; both read correct fused rows.
        // Zero-padded table removes y masking; x masking collapses to
        // wxe = clamp(min(ix+1, 614-ix), 0, 1).
        const uint2* __restrict__ colB =
            (const uint2*)((const char*)(g_colh + PADR) - (unsigned long long)MAGICI * 8ULL);
        #pragma unroll 2
        for (int a = 0; a < A_N; ++a, colB += HPP) {
            float2 cs = sh_cs[a];
            float c = cs.x, s = cs.y;
            float ix  = fmaf(c, Xp, fmaf(-s, Yp, 306.5f));
            float iy2 = fmaf(s, Xp, fmaf(c, Yp, 306.0f));            // iy - 0.5
            float wxe = fmaxf(fminf(fminf(ix + 1.0f, 614.0f - ix), 1.0f), 0.0f);
            float fq  = iy2 + MAGICF;
            float qf  = fq - MAGICF;
            float w   = (iy2 - qf) + 0.5f;
            uint2 cc  = colB[__float_as_uint(fq)];
            float2 rf = __half22float2(lerp_h2(cc, w));
            a0x = fmaf(wxe, rf.x, a0x);
            a0y = fmaf(wxe, rf.y, a0y);
        }
    }

    const float scale = (float)(1.0 / (180.0 + 1e-6));
    int o = y * HOUT + x;
    out[o]               = (a0x + a1x) * scale;
    out[o + HOUT * HOUT] = (a0y + a1y) * scale;   // batch 1 (out shape (2,1,512,512))
}

extern "C" void kernel_launch(void* const* d_in, const int* in_sizes, int n_in,
                              void* d_out, int out_size) {
    const float* sino   = (const float*)d_in[0];
    const float* angles = (const float*)d_in[1];
    float* out = (float*)d_out;

    col_kernel<<<(A_N * HPP + 255) / 256, 256>>>(sino);

    dim3 blk(32, 8);
    dim3 grd(HOUT / 32, HOUT / 8);   // 16 x 64 = 1024 CTAs, single resident wave
    bp_kernel<<<grd, blk>>>(angles, out);
}

// round 16
// speedup vs baseline: 1.6530x; 1.0862x over previous
#include <cuda_runtime.h>
#include <cuda_fp16.h>

// BackProjection: B=2, A=180, HR=512, H=W=512, pad=51, Hp=Wp=614
#define A_N   180
#define HR_N  512
#define HOUT  512
#define HP    614
#define PADR  64            // zero-pad rows each side (covers y0 in [-56, 667])
#define HPP   (HP + 2*PADR) // 742 rows per angle
#define MAGICF 12582912.0f  // 1.5 * 2^23
#define MAGICI 0x4B400000u  // float bits of 12582912.0f

// Zero-padded per-angle column profile in fp16, DELTA form:
// entry.x = half2(b0[y], b1[y]);  entry.y = half2(b0[y+1]-b0[y], b1[y+1]-b1[y])
// with b*[y] == 0 outside [0, HP-1]. Bilinear-y = one HFMA2 on entry.
__device__ uint2 g_colh[A_N * HPP];

__device__ __forceinline__ float2 col_at(const float* __restrict__ sino, int a, int y) {
    if (y < 0 || y >= HP) return make_float2(0.f, 0.f);
    float src = ((float)y + 0.5f) * ((float)HR_N / (float)HP) - 0.5f;
    src = fminf(fmaxf(src, 0.0f), (float)(HR_N - 1));
    int i0 = (int)src;                       // src >= 0
    int i1 = min(i0 + 1, HR_N - 1);
    float w = src - (float)i0;
    const float* s0 = sino + a * HR_N;                 // b = 0
    const float* s1 = sino + A_N * HR_N + a * HR_N;    // b = 1
    // match reference rounding: p0*(1-w) + p1*w
    float v0 = s0[i0] * (1.0f - w) + s0[i1] * w;
    float v1 = s1[i0] * (1.0f - w) + s1[i1] * w;
    return make_float2(v0, v1);
}

__global__ void col_kernel(const float* __restrict__ sino) {
    int idx = blockIdx.x * blockDim.x + threadIdx.x;
    if (idx >= A_N * HPP) return;
    int a  = idx / HPP;
    int y  = idx - a * HPP - PADR;          // logical row
    float2 c0 = col_at(sino, a, y);
    float2 c1 = col_at(sino, a, y + 1);
    __half2 h0 = __floats2half2_rn(c0.x, c0.y);
    __half2 hd = __floats2half2_rn(c1.x - c0.x, c1.y - c0.y);
    uint2 e;
    e.x = *reinterpret_cast<unsigned*>(&h0);
    e.y = *reinterpret_cast<unsigned*>(&hd);
    g_colh[idx] = e;
}

// lerp with delta-form entry: val + w * delta, both batches in one HFMA2.
__device__ __forceinline__ __half2 lerp_h2(uint2 cc, float w) {
    __half2 lo = *reinterpret_cast<__half2*>(&cc.x);
    __half2 dh = *reinterpret_cast<__half2*>(&cc.y);
    return __hfma2(dh, __float2half2_rn(w), lo);
}

__global__ __launch_bounds__(256, 7) void bp_kernel(const float* __restrict__ angles,
                                                    float* __restrict__ out) {
    __shared__ __align__(16) float2 sh_cs[A_N];   // (cos, sin) of th = -deg2rad(angle)
    int t = threadIdx.y * 32 + threadIdx.x;
    if (t < A_N) {
        float th = -angles[t] * 0.017453292519943295f;
        sh_cs[t] = make_float2(cosf(th), sinf(th));
    }
    __syncthreads();

    // 32x1 warp layout (proven best): coalesced loads/stores, 1 pixel/thread.
    int x = blockIdx.x * 32 + threadIdx.x;
    int y = blockIdx.y * 8 + threadIdx.y;
    // padded coords (x+51), center 306.5:  X = (x+51) - 306.5 = x - 255.5
    float Xp = (float)x - 255.5f;
    float Yp = (float)y - 255.5f;

    float accx = 0.0f, accy = 0.0f;

    // Interior: r^2 < 93500 (r < 305.8) => ix, iy in (0.5, 612.5) for all
    // angles: no masking, wxe == 1, y0 in [0,612]. Warp-uniform branch so a
    // straddling warp executes exactly ONE of the two loops.
    bool interior = fmaf(Xp, Xp, Yp * Yp) < 93500.0f;

    if (__all_sync(0xffffffffu, interior)) {
        const uint2* __restrict__ colA = g_colh + PADR;
        const float4* __restrict__ cs4 = reinterpret_cast<const float4*>(sh_cs);
        #pragma unroll 4
        for (int a2 = 0; a2 < A_N / 2; ++a2, colA += 2 * HPP) {
            float4 p = cs4[a2];             // (c0, s0, c1, s1) — one LDS.128
            float iy0 = fmaf(p.y, Xp, fmaf(p.x, Yp, 306.5f));
            float iy1 = fmaf(p.w, Xp, fmaf(p.z, Yp, 306.5f));
            int   q0 = (int)iy0;            // iy > 0 -> trunc == floor
            int   q1 = (int)iy1;
            float w0 = iy0 - (float)q0;
            float w1 = iy1 - (float)q1;
            uint2 cc0 = colA[q0];
            uint2 cc1 = colA[HPP + q1];
            __half2 r0 = lerp_h2(cc0, w0);
            __half2 r1 = lerp_h2(cc1, w1);
            __half2 rs = __hadd2(r0, r1);   // pair-sum in half, flush to fp32
            float2 rf = __half22float2(rs);
            accx += rf.x;
            accy += rf.y;
        }
    } else {
        // General/corner path (tail-setting stragglers): magic-number floor
        // removes the serial CVT chain. fq = (iy-0.5) + 1.5*2^23 -> low
        // mantissa bits encode floor(iy); bias MAGICI folded into the base
        // pointer. Round-to-even ties give w=0 or w=1; delta form handles
        // both correctly. Zero-padded table removes y masking; x masking
        // collapses to wxe = clamp(min(ix+1, 614-ix), 0, 1).
        const uint2* __restrict__ colB =
            (const uint2*)((const char*)(g_colh + PADR) - (unsigned long long)MAGICI * 8ULL);
        #pragma unroll 2
        for (int a = 0; a < A_N; ++a, colB += HPP) {
            float2 cs = sh_cs[a];
            float c = cs.x, s = cs.y;
            float ix  = fmaf(c, Xp, fmaf(-s, Yp, 306.5f));
            float iy2 = fmaf(s, Xp, fmaf(c, Yp, 306.0f));            // iy - 0.5
            float wxe = fmaxf(fminf(fminf(ix + 1.0f, 614.0f - ix), 1.0f), 0.0f);
            float fq  = iy2 + MAGICF;
            float qf  = fq - MAGICF;
            float w   = (iy2 - qf) + 0.5f;
            uint2 cc  = colB[__float_as_uint(fq)];
            float2 rf = __half22float2(lerp_h2(cc, w));
            accx = fmaf(wxe, rf.x, accx);
            accy = fmaf(wxe, rf.y, accy);
        }
    }

    const float scale = (float)(1.0 / (180.0 + 1e-6));
    int o = y * HOUT + x;
    out[o]               = accx * scale;
    out[o + HOUT * HOUT] = accy * scale;   // batch 1 (out shape (2,1,512,512))
}

extern "C" void kernel_launch(void* const* d_in, const int* in_sizes, int n_in,
                              void* d_out, int out_size) {
    const float* sino   = (const float*)d_in[0];
    const float* angles = (const float*)d_in[1];
    float* out = (float*)d_out;

    col_kernel<<<(A_N * HPP + 255) / 256, 256>>>(sino);

    dim3 blk(32, 8);
    dim3 grd(HOUT / 32, HOUT / 8);   // 16 x 64 = 1024 CTAs, single resident wave
    bp_kernel<<<grd, blk>>>(angles, out);
}

// round 17
// speedup vs baseline: 1.7408x; 1.0531x over previous
#include <cuda_runtime.h>
#include <cuda_fp16.h>

// BackProjection: B=2, A=180, HR=512, H=W=512, pad=51, Hp=Wp=614
#define A_N   180
#define HR_N  512
#define HOUT  512
#define HP    614
#define PADR  64            // zero-pad rows each side (covers y0 in [-56, 667])
#define HPP   (HP + 2*PADR) // 742 rows per angle
#define MAGICF 12582912.0f  // 1.5 * 2^23
#define MAGICI 0x4B400000u  // float bits of 12582912.0f

// Zero-padded per-angle column profile in fp16, MIDPOINT/DELTA form:
// entry.x = half2(mid0, mid1),  mid = 0.5*(col[y] + col[y+1])
// entry.y = half2(d0, d1),      d   = col[y+1] - col[y]
// value at fractional w in [0,1): col[y] + w*d = mid + (w-0.5)*d.
// With magic-floor producing w' = iy2 - qf in [-0.5, 0.5), value = mid + w'*d
// in ONE HFMA2 — no +0.5 correction needed. Ties (w'=±0.5 boundary) give
// exactly col[y+1] from either neighboring entry.
__device__ uint2 g_colh[A_N * HPP];

__device__ __forceinline__ float2 col_at(const float* __restrict__ sino, int a, int y) {
    if (y < 0 || y >= HP) return make_float2(0.f, 0.f);
    float src = ((float)y + 0.5f) * ((float)HR_N / (float)HP) - 0.5f;
    src = fminf(fmaxf(src, 0.0f), (float)(HR_N - 1));
    int i0 = (int)src;                       // src >= 0
    int i1 = min(i0 + 1, HR_N - 1);
    float w = src - (float)i0;
    const float* s0 = sino + a * HR_N;                 // b = 0
    const float* s1 = sino + A_N * HR_N + a * HR_N;    // b = 1
    // match reference rounding: p0*(1-w) + p1*w
    float v0 = s0[i0] * (1.0f - w) + s0[i1] * w;
    float v1 = s1[i0] * (1.0f - w) + s1[i1] * w;
    return make_float2(v0, v1);
}

__global__ void col_kernel(const float* __restrict__ sino) {
    int idx = blockIdx.x * blockDim.x + threadIdx.x;
    if (idx >= A_N * HPP) return;
    int a  = idx / HPP;
    int y  = idx - a * HPP - PADR;          // logical row
    float2 c0 = col_at(sino, a, y);
    float2 c1 = col_at(sino, a, y + 1);
    __half2 hm = __floats2half2_rn(0.5f * (c0.x + c1.x), 0.5f * (c0.y + c1.y));
    __half2 hd = __floats2half2_rn(c1.x - c0.x, c1.y - c0.y);
    uint2 e;
    e.x = *reinterpret_cast<unsigned*>(&hm);
    e.y = *reinterpret_cast<unsigned*>(&hd);
    g_colh[idx] = e;
}

// lerp with midpoint/delta entry: mid + w' * delta, both batches in one HFMA2.
__device__ __forceinline__ __half2 lerp_h2(uint2 cc, float wp) {
    __half2 mid = *reinterpret_cast<__half2*>(&cc.x);
    __half2 dh  = *reinterpret_cast<__half2*>(&cc.y);
    return __hfma2(dh, __float2half2_rn(wp), mid);
}

__global__ __launch_bounds__(256, 7) void bp_kernel(const float* __restrict__ angles,
                                                    float* __restrict__ out) {
    __shared__ float2 sh_cs[A_N];   // (cos, sin) of th = -deg2rad(angle)
    int t = threadIdx.y * 32 + threadIdx.x;
    if (t < A_N) {
        float th = -angles[t] * 0.017453292519943295f;
        sh_cs[t] = make_float2(cosf(th), sinf(th));
    }
    __syncthreads();

    // 32x1 warp layout (proven best): coalesced loads/stores, 1 pixel/thread.
    int x = blockIdx.x * 32 + threadIdx.x;
    int y = blockIdx.y * 8 + threadIdx.y;
    // padded coords (x+51), center 306.5:  X = (x+51) - 306.5 = x - 255.5
    float Xp = (float)x - 255.5f;
    float Yp = (float)y - 255.5f;

    float accx = 0.0f, accy = 0.0f;

    // Magic-floor: iy2 = iy - 0.5 (fold -0.5 into the 306.0 constant);
    // fq = RN(iy2 + 1.5*2^23) -> low bits of fq encode round(iy2) = floor(iy);
    // qf = fq - MAGIC exact; w' = iy2 - qf in [-0.5, 0.5). Bias MAGICI folded
    // into the base pointer so the gather address is one IMAD.WIDE from the
    // raw float bits. Removes the serial F2I/I2F (~40 cyc) from the chain.
    const uint2* __restrict__ colB0 =
        (const uint2*)((const char*)(g_colh + PADR) - (unsigned long long)MAGICI * 8ULL);

    // Interior: r^2 < 93500 (r < 305.8) => ix, iy in (0.5, 612.5) for all
    // angles: no masking, wxe == 1, q in [0,612]. Warp-uniform branch.
    bool interior = fmaf(Xp, Xp, Yp * Yp) < 93500.0f;

    if (__all_sync(0xffffffffu, interior)) {
        const uint2* __restrict__ colB = colB0;
        #pragma unroll 4
        for (int a = 0; a < A_N; a += 2, colB += 2 * HPP) {
            float2 cs0 = sh_cs[a];
            float2 cs1 = sh_cs[a + 1];
            float iy20 = fmaf(cs0.y, Xp, fmaf(cs0.x, Yp, 306.0f));   // iy - 0.5
            float iy21 = fmaf(cs1.y, Xp, fmaf(cs1.x, Yp, 306.0f));
            float fq0 = iy20 + MAGICF;
            float fq1 = iy21 + MAGICF;
            float w0  = iy20 - (fq0 - MAGICF);
            float w1  = iy21 - (fq1 - MAGICF);
            uint2 cc0 = colB[__float_as_uint(fq0)];
            uint2 cc1 = (colB + HPP)[__float_as_uint(fq1)];
            __half2 r0 = lerp_h2(cc0, w0);
            __half2 r1 = lerp_h2(cc1, w1);
            __half2 rs = __hadd2(r0, r1);   // pair-sum in half, flush to fp32
            float2 rf = __half22float2(rs);
            accx += rf.x;
            accy += rf.y;
        }
    } else {
        // General/corner path. Zero-padded table removes y masking; x masking
        // collapses to wxe = clamp(min(ix+1, 614-ix), 0, 1). Magic floor works
        // for negative floor(iy) too (q in [-55,667]; bits stay positive).
        const uint2* __restrict__ colB = colB0;
        #pragma unroll 2
        for (int a = 0; a < A_N; ++a, colB += HPP) {
            float2 cs = sh_cs[a];
            float c = cs.x, s = cs.y;
            float ix  = fmaf(c, Xp, fmaf(-s, Yp, 306.5f));
            float iy2 = fmaf(s, Xp, fmaf(c, Yp, 306.0f));            // iy - 0.5
            float wxe = fmaxf(fminf(fminf(ix + 1.0f, 614.0f - ix), 1.0f), 0.0f);
            float fq  = iy2 + MAGICF;
            float w   = iy2 - (fq - MAGICF);
            uint2 cc  = colB[__float_as_uint(fq)];
            float2 rf = __half22float2(lerp_h2(cc, w));
            accx = fmaf(wxe, rf.x, accx);
            accy = fmaf(wxe, rf.y, accy);
        }
    }

    const float scale = (float)(1.0 / (180.0 + 1e-6));
    int o = y * HOUT + x;
    out[o]               = accx * scale;
    out[o + HOUT * HOUT] = accy * scale;   // batch 1 (out shape (2,1,512,512))
}

extern "C" void kernel_launch(void* const* d_in, const int* in_sizes, int n_in,
                              void* d_out, int out_size) {
    const float* sino   = (const float*)d_in[0];
    const float* angles = (const float*)d_in[1];
    float* out = (float*)d_out;

    col_kernel<<<(A_N * HPP + 255) / 256, 256>>>(sino);

    dim3 blk(32, 8);
    dim3 grd(HOUT / 32, HOUT / 8);   // 16 x 64 = 1024 CTAs, single resident wave
    bp_kernel<<<grd, blk>>>(angles, out);
}